// round 12
// baseline (speedup 1.0000x reference)
#include <cuda_runtime.h>
#include <cuda_fp16.h>
#include <math.h>
#include <stdint.h>
#include <string.h>

// Problem constants:
#define B_ 64
#define S_ 2048
#define D_ 512
#define U_ 512
#define BS_ (B_ * S_)

#define KT 16                 // k-chunk depth
#define NKT (D_ / KT)         // 32 chunks
#define NTILE 256             // u-cols per block
#define ASTR 24               // A smem row stride in halves (16 + 8 pad)
#define BSTR 24               // B smem row stride in halves
#define BBUF (NTILE * BSTR)   // halves per B stage

// -------- scratch (device globals; no allocation allowed) --------
__device__ float  g_sh2[B_ * U_];        // dec@Ws + bs + bh + bc   (B,U)
__device__ __half g_WhTh[U_ * D_];       // Wh transposed+fp16: [u][d]
__device__ float  g_scorep[2 * BS_];     // per-u-slice partial scores
__device__ float  g_ctxp[32 * B_ * D_];  // partial contexts

// fast tanh via MUFU.TANH. rel err ~2^-10.7.
__device__ __forceinline__ float tanh_fast(float x) {
    float y; asm("tanh.approx.f32 %0, %1;" : "=f"(y) : "f"(x)); return y;
}

// bit-cast __half2 -> uint32 (memcpy folds to a register reinterpretation)
__device__ __forceinline__ uint32_t h2_to_u32(__half2 h) {
    uint32_t u;
    memcpy(&u, &h, 4);
    return u;
}

__device__ __forceinline__ void mma_f16(
    float& c0, float& c1, float& c2, float& c3,
    uint32_t a0, uint32_t a1, uint32_t a2, uint32_t a3,
    uint32_t b0, uint32_t b1)
{
    asm volatile(
        "mma.sync.aligned.m16n8k16.row.col.f32.f16.f16.f32 "
        "{%0,%1,%2,%3}, {%4,%5,%6,%7}, {%8,%9}, {%0,%1,%2,%3};\n"
        : "+f"(c0), "+f"(c1), "+f"(c2), "+f"(c3)
        : "r"(a0), "r"(a1), "r"(a2), "r"(a3), "r"(b0), "r"(b1));
}

__device__ __forceinline__ void cp_async16(void* smem_dst, const void* gsrc) {
    uint32_t sa = (uint32_t)__cvta_generic_to_shared(smem_dst);
    asm volatile("cp.async.cg.shared.global [%0], [%1], 16;\n" :: "r"(sa), "l"(gsrc));
}
#define CP_COMMIT() asm volatile("cp.async.commit_group;\n" ::: "memory")
#define CP_WAIT(n)  asm volatile("cp.async.wait_group %0;\n" :: "n"(n) : "memory")

// ============================================================================
// Kernel 0: Wh[d][u] -> g_WhTh[u][d] (transpose + fp16 convert). 512x512.
// ============================================================================
__global__ __launch_bounds__(256) void k_prepWh(const float* __restrict__ Wh)
{
    __shared__ float t[32][33];
    int k0 = blockIdx.x * 32, u0 = blockIdx.y * 32;
    int tx = threadIdx.x & 31, ty = threadIdx.x >> 5;   // 32 x 8
    #pragma unroll
    for (int j = 0; j < 4; ++j)
        t[ty + j * 8][tx] = Wh[(size_t)(k0 + ty + j * 8) * U_ + u0 + tx];
    __syncthreads();
    #pragma unroll
    for (int j = 0; j < 4; ++j)
        g_WhTh[(size_t)(u0 + ty + j * 8) * D_ + k0 + tx] = __float2half_rn(t[tx][ty + j * 8]);
}

// ============================================================================
// Kernel 1: sh2[b,u] = dec[b,:]@Ws[:,u] + bs[u] + bh[u] + bc[u]
// ============================================================================
__global__ __launch_bounds__(256) void k_sh2(
    const float* __restrict__ dec, const float* __restrict__ Ws,
    const float* __restrict__ bs, const float* __restrict__ bh,
    const float* __restrict__ bc)
{
    __shared__ float decs[D_];
    int b = blockIdx.x;
    int tid = threadIdx.x;
    for (int d = tid; d < D_; d += 256) decs[d] = dec[b * D_ + d];
    __syncthreads();
    for (int u = tid; u < U_; u += 256) {
        float acc = bs[u] + bh[u] + bc[u];
        #pragma unroll 8
        for (int d = 0; d < D_; ++d)
            acc = fmaf(decs[d], Ws[d * U_ + u], acc);
        g_sh2[b * U_ + u] = acc;
    }
}

// ============================================================================
// Kernel 2: fp16 tensor-core score GEMM (m16n8k16), fused tanh/Vw epilogue.
//   partial[nb][b,s] = sum_{u in 256-slice nb} Vw[u]*tanh(enc@Wh + sh2 + cov*Wc)
// Block 128(s) x 256(u), 512 threads = 16 warps (2m x 8n), warp tile 64x32
// (4mt x 4nt m16n8k16). K-chunks of 16 (one k16 MMA step per chunk):
// A = LDG fp32 -> cvt-at-load -> STS fp16 (single buffer, reg prefetch);
// B = cp.async fp16 from g_WhTh, double-buffered. ALL smem static: 38.4 KB
// total < 48 KB default carve-out -> plain launch, graph-capture safe.
// blockIdx.x = mb*2 + nb (nb fastest -> enc tile shared via L2).
// ============================================================================
__global__ __launch_bounds__(512) void k_score_f16(
    const float* __restrict__ enc, const float* __restrict__ cov,
    const float* __restrict__ Wc, const float* __restrict__ Vw)
{
    __shared__ __half Ash[128 * ASTR];       // 6 KB
    __shared__ __half Bsh[2][BBUF];          // 2 x 12 KB
    __shared__ float covs[128];
    __shared__ float sh2s[NTILE], Wcs[NTILE], Vws[NTILE];
    __shared__ float red[128][8];

    const int tid  = threadIdx.x;
    const int lane = tid & 31;
    const int warp = tid >> 5;           // 0..15
    const int wm   = warp >> 3;          // 0..1 -> 64-row slice
    const int wn   = warp & 7;           // 0..7 -> 32-col slice

    const int gb = blockIdx.x;
    const int nb = gb & 1;               // u-slice (256 wide)
    const int mb = gb >> 1;
    const int b  = mb >> 4;              // 16 m-blocks per batch
    const int s0 = (mb & 15) * 128;
    const int u0 = nb * NTILE;

    const float*  X  = enc + ((size_t)b * S_ + s0) * D_;
    const __half* Bg = g_WhTh + (size_t)u0 * D_;

    if (tid < 128) covs[tid] = cov[(size_t)b * S_ + s0 + tid];
    if (tid >= 256) {
        int u = tid - 256;
        sh2s[u] = g_sh2[b * U_ + u0 + u];
        Wcs[u]  = Wc[u0 + u];
        Vws[u]  = Vw[u0 + u];
    }

    float acc[4][4][4];
    #pragma unroll
    for (int mt = 0; mt < 4; ++mt)
        #pragma unroll
        for (int nt = 0; nt < 4; ++nt)
            #pragma unroll
            for (int i = 0; i < 4; ++i) acc[mt][nt][i] = 0.f;

    // A prefetch: 1 slot/thread (128 rows x 4 quads = 512 slots), cvt at load
    const int arow = tid >> 2, aq = tid & 3;
    uint2 av;
    {
        float4 v = *(const float4*)(X + (size_t)arow * D_ + aq * 4);
        av.x = h2_to_u32(__floats2half2_rn(v.x, v.y));
        av.y = h2_to_u32(__floats2half2_rn(v.z, v.w));
    }
    // B chunk 0: 256 rows x 2 segs of 16B = 512 slots, 1/thread
    const int brow = tid >> 1, bseg = tid & 1;
    cp_async16(&Bsh[0][brow * BSTR + bseg * 8], Bg + (size_t)brow * D_ + bseg * 8);
    CP_COMMIT();

    for (int kt = 0; kt < NKT; ++kt) {
        const int cur = kt & 1;
        __syncthreads();   // all warps done reading Ash (iter kt-1)
        // store A(kt) fp16 into Ash
        *(uint2*)&Ash[arow * ASTR + aq * 4] = av;
        if (kt + 1 < NKT) {
            // prefetch A(kt+1) into regs (cvt at load)
            float4 v = *(const float4*)(X + (size_t)arow * D_ + (kt + 1) * KT + aq * 4);
            av.x = h2_to_u32(__floats2half2_rn(v.x, v.y));
            av.y = h2_to_u32(__floats2half2_rn(v.z, v.w));
            // B(kt+1) cp.async into other buffer
            cp_async16(&Bsh[cur ^ 1][brow * BSTR + bseg * 8],
                       Bg + (size_t)brow * D_ + (kt + 1) * KT + bseg * 8);
            CP_COMMIT();
            CP_WAIT(1);    // B(kt) arrived
        } else {
            CP_WAIT(0);
        }
        __syncthreads();

        const __half* Bc = Bsh[cur];
        // one k16 MMA step per chunk
        {
            const int c = 2 * (lane & 3);
            uint32_t a[4][4];
            #pragma unroll
            for (int mt = 0; mt < 4; ++mt) {
                int r = wm * 64 + mt * 16 + (lane >> 2);
                a[mt][0] = *(const uint32_t*)&Ash[r * ASTR + c];
                a[mt][1] = *(const uint32_t*)&Ash[(r + 8) * ASTR + c];
                a[mt][2] = *(const uint32_t*)&Ash[r * ASTR + c + 8];
                a[mt][3] = *(const uint32_t*)&Ash[(r + 8) * ASTR + c + 8];
            }
            uint32_t bf[4][2];
            #pragma unroll
            for (int nt = 0; nt < 4; ++nt) {
                int n = wn * 32 + nt * 8 + (lane >> 2);
                bf[nt][0] = *(const uint32_t*)&Bc[n * BSTR + c];
                bf[nt][1] = *(const uint32_t*)&Bc[n * BSTR + c + 8];
            }
            #pragma unroll
            for (int mt = 0; mt < 4; ++mt)
                #pragma unroll
                for (int nt = 0; nt < 4; ++nt)
                    mma_f16(acc[mt][nt][0], acc[mt][nt][1],
                            acc[mt][nt][2], acc[mt][nt][3],
                            a[mt][0], a[mt][1], a[mt][2], a[mt][3],
                            bf[nt][0], bf[nt][1]);
        }
    }

    // --- epilogue: e -> tanh -> *Vw -> per-row partial sums ---
    float psum[8];
    #pragma unroll
    for (int i = 0; i < 8; ++i) psum[i] = 0.f;
    #pragma unroll
    for (int mt = 0; mt < 4; ++mt) {
        int r_lo = wm * 64 + mt * 16 + (lane >> 2);
        float cv_lo = covs[r_lo];
        float cv_hi = covs[r_lo + 8];
        #pragma unroll
        for (int nt = 0; nt < 4; ++nt) {
            int uc = wn * 32 + nt * 8 + 2 * (lane & 3);
            #pragma unroll
            for (int j = 0; j < 2; ++j) {
                float s2 = sh2s[uc + j], wc = Wcs[uc + j], vw = Vws[uc + j];
                float e0 = acc[mt][nt][j]     + s2 + cv_lo * wc;
                float e1 = acc[mt][nt][2 + j] + s2 + cv_hi * wc;
                psum[2 * mt]     = fmaf(vw, tanh_fast(e0), psum[2 * mt]);
                psum[2 * mt + 1] = fmaf(vw, tanh_fast(e1), psum[2 * mt + 1]);
            }
        }
    }
    #pragma unroll
    for (int i = 0; i < 8; ++i) {
        psum[i] += __shfl_xor_sync(0xffffffff, psum[i], 1);
        psum[i] += __shfl_xor_sync(0xffffffff, psum[i], 2);
    }
    __syncthreads();
    if ((lane & 3) == 0) {
        #pragma unroll
        for (int mt = 0; mt < 4; ++mt) {
            int r = wm * 64 + mt * 16 + (lane >> 2);
            red[r][wn]     = psum[2 * mt];
            red[r + 8][wn] = psum[2 * mt + 1];
        }
    }
    __syncthreads();
    if (tid < 128) {
        float s = 0.f;
        #pragma unroll
        for (int t = 0; t < 8; ++t) s += red[tid][t];
        g_scorep[(size_t)nb * BS_ + (size_t)b * S_ + s0 + tid] = s;
    }
}

// ============================================================================
// Kernel 3: fold 2 score partials; masked renormalized softmax + coverage.
// ============================================================================
__global__ __launch_bounds__(1024) void k_softmax(
    const float* __restrict__ mask, const float* __restrict__ cov,
    float* __restrict__ attn_out, float* __restrict__ cov_out)
{
    __shared__ float sred[1024];
    __shared__ float ps[S_];
    int b = blockIdx.x;
    int tid = threadIdx.x;

    float m = -1e30f;
    for (int s = tid; s < S_; s += 1024) {
        float sc = g_scorep[(size_t)b * S_ + s] + g_scorep[BS_ + (size_t)b * S_ + s];
        ps[s] = sc;
        m = fmaxf(m, sc);
    }
    sred[tid] = m; __syncthreads();
    for (int off = 512; off; off >>= 1) {
        if (tid < off) sred[tid] = fmaxf(sred[tid], sred[tid + off]);
        __syncthreads();
    }
    m = sred[0]; __syncthreads();

    float sum = 0.f;
    for (int s = tid; s < S_; s += 1024) {
        float p = expf(ps[s] - m) * mask[(size_t)b * S_ + s];
        ps[s] = p;
        sum += p;
    }
    sred[tid] = sum; __syncthreads();
    for (int off = 512; off; off >>= 1) {
        if (tid < off) sred[tid] += sred[tid + off];
        __syncthreads();
    }
    float inv = 1.f / sred[0];

    for (int s = tid; s < S_; s += 1024) {
        float a = ps[s] * inv;
        attn_out[(size_t)b * S_ + s] = a;
        cov_out[(size_t)b * S_ + s]  = a + cov[(size_t)b * S_ + s];
    }
}

// ============================================================================
// Kernel 4: partial context over 32 s-chunks of 64.
// ============================================================================
__global__ __launch_bounds__(128) void k_ctx(
    const float* __restrict__ enc, const float* __restrict__ attn)
{
    __shared__ float as[64];
    int b = blockIdx.x;
    int ch = blockIdx.y;
    int tid = threadIdx.x;
    int s0 = ch * 64;
    if (tid < 64) as[tid] = attn[(size_t)b * S_ + s0 + tid];
    __syncthreads();

    const float4* ep = (const float4*)(enc + ((size_t)b * S_ + s0) * D_) + tid;
    float4 acc = make_float4(0.f, 0.f, 0.f, 0.f);
    #pragma unroll 8
    for (int s = 0; s < 64; ++s) {
        float a = as[s];
        float4 v = ep[(size_t)s * (D_ / 4)];
        acc.x = fmaf(a, v.x, acc.x);
        acc.y = fmaf(a, v.y, acc.y);
        acc.z = fmaf(a, v.z, acc.z);
        acc.w = fmaf(a, v.w, acc.w);
    }
    *(float4*)&g_ctxp[((size_t)ch * B_ + b) * D_ + tid * 4] = acc;
}

__global__ __launch_bounds__(256) void k_ctx_red(float* __restrict__ ctx_out)
{
    int i = blockIdx.x * 256 + threadIdx.x;
    if (i < B_ * D_) {
        float s = 0.f;
        #pragma unroll
        for (int c = 0; c < 32; ++c) s += g_ctxp[c * B_ * D_ + i];
        ctx_out[i] = s;
    }
}

// ============================================================================
// launch
// ============================================================================
extern "C" void kernel_launch(void* const* d_in, const int* in_sizes, int n_in,
                              void* d_out, int out_size)
{
    const float* dec  = (const float*)d_in[0];   // (B,D)
    const float* enc  = (const float*)d_in[1];   // (B,S,D)
    const float* mask = (const float*)d_in[2];   // (B,S)
    const float* cov  = (const float*)d_in[3];   // (B,S,1)
    const float* Wh   = (const float*)d_in[4];   // (D,U)
    const float* bh   = (const float*)d_in[5];   // (U)
    const float* Ws   = (const float*)d_in[6];   // (D,U)
    const float* bs   = (const float*)d_in[7];   // (U)
    const float* Wc   = (const float*)d_in[8];   // (1,U)
    const float* bc   = (const float*)d_in[9];   // (U)
    const float* Vw   = (const float*)d_in[10];  // (U,1)
    // d_in[11] = bv: constant shift, cancels under renormalized softmax.

    float* out_ctx  = (float*)d_out;                     // (B,D)
    float* out_attn = (float*)d_out + B_ * D_;           // (B,S)
    float* out_cov  = (float*)d_out + B_ * D_ + B_ * S_; // (B,S,1)

    k_prepWh<<<dim3(16, 16), 256>>>(Wh);
    k_sh2<<<B_, 256>>>(dec, Ws, bs, bh, bc);
    k_score_f16<<<(BS_ / 128) * 2, 512>>>(enc, cov, Wc, Vw);
    k_softmax<<<B_, 1024>>>(mask, cov, out_attn, out_cov);
    k_ctx<<<dim3(B_, 32), 128>>>(enc, out_attn);
    k_ctx_red<<<(B_ * D_ + 255) / 256, 256>>>(out_ctx);
}

// round 13
// speedup vs baseline: 1.6810x; 1.6810x over previous
#include <cuda_runtime.h>
#include <cuda_fp16.h>
#include <math.h>
#include <stdint.h>

// Problem constants:
#define B_ 64
#define S_ 2048
#define D_ 512
#define U_ 512
#define BS_ (B_ * S_)

#define KT 32                 // k-chunk depth
#define NKT (D_ / KT)         // 16 chunks
#define ASTR 40               // A smem row stride in halves (32 + 8 pad)
#define BSTR 40               // B smem row stride in halves

// -------- scratch (device globals; no allocation allowed) --------
__device__ float  g_sh2[B_ * U_];        // dec@Ws + bs + bh + bc   (B,U)
__device__ __half g_WhTh[U_ * D_];       // Wh transposed+fp16: [u][d]
__device__ float  g_scorep[4 * BS_];     // per-u-slice partial scores
__device__ float  g_ctxp[32 * B_ * D_];  // partial contexts

// fast tanh via MUFU.TANH. rel err ~2^-10.7.
__device__ __forceinline__ float tanh_fast(float x) {
    float y; asm("tanh.approx.f32 %0, %1;" : "=f"(y) : "f"(x)); return y;
}

__device__ __forceinline__ void mma_f16(
    float& c0, float& c1, float& c2, float& c3,
    uint32_t a0, uint32_t a1, uint32_t a2, uint32_t a3,
    uint32_t b0, uint32_t b1)
{
    asm volatile(
        "mma.sync.aligned.m16n8k16.row.col.f32.f16.f16.f32 "
        "{%0,%1,%2,%3}, {%4,%5,%6,%7}, {%8,%9}, {%0,%1,%2,%3};\n"
        : "+f"(c0), "+f"(c1), "+f"(c2), "+f"(c3)
        : "r"(a0), "r"(a1), "r"(a2), "r"(a3), "r"(b0), "r"(b1));
}

__device__ __forceinline__ void cp_async16(void* smem_dst, const void* gsrc) {
    uint32_t sa = (uint32_t)__cvta_generic_to_shared(smem_dst);
    asm volatile("cp.async.cg.shared.global [%0], [%1], 16;\n" :: "r"(sa), "l"(gsrc));
}
#define CP_COMMIT() asm volatile("cp.async.commit_group;\n" ::: "memory")
#define CP_WAIT(n)  asm volatile("cp.async.wait_group %0;\n" :: "n"(n) : "memory")

// ============================================================================
// Kernel 0: Wh[d][u] -> g_WhTh[u][d] (transpose + fp16 convert). 512x512.
// ============================================================================
__global__ __launch_bounds__(256) void k_prepWh(const float* __restrict__ Wh)
{
    __shared__ float t[32][33];
    int k0 = blockIdx.x * 32, u0 = blockIdx.y * 32;
    int tx = threadIdx.x & 31, ty = threadIdx.x >> 5;   // 32 x 8
    #pragma unroll
    for (int j = 0; j < 4; ++j)
        t[ty + j * 8][tx] = Wh[(size_t)(k0 + ty + j * 8) * U_ + u0 + tx];
    __syncthreads();
    #pragma unroll
    for (int j = 0; j < 4; ++j)
        g_WhTh[(size_t)(u0 + ty + j * 8) * D_ + k0 + tx] = __float2half_rn(t[tx][ty + j * 8]);
}

// ============================================================================
// Kernel 1: sh2[b,u] = dec[b,:]@Ws[:,u] + bs[u] + bh[u] + bc[u]
// grid (B, 4): each block handles a 128-wide u-slice (4x parallelism vs R8).
// ============================================================================
__global__ __launch_bounds__(128) void k_sh2(
    const float* __restrict__ dec, const float* __restrict__ Ws,
    const float* __restrict__ bs, const float* __restrict__ bh,
    const float* __restrict__ bc)
{
    __shared__ float decs[D_];
    int b = blockIdx.x;
    int u0 = blockIdx.y * 128;
    int tid = threadIdx.x;
    for (int d = tid; d < D_; d += 128) decs[d] = dec[b * D_ + d];
    __syncthreads();
    int u = u0 + tid;
    float acc = bs[u] + bh[u] + bc[u];
    #pragma unroll 8
    for (int d = 0; d < D_; ++d)
        acc = fmaf(decs[d], Ws[d * U_ + u], acc);
    g_sh2[b * U_ + u] = acc;
}

// ============================================================================
// Kernel 2: fp16 tensor-core score GEMM (m16n8k16), fused tanh/Vw epilogue.
// BYTE-IDENTICAL to the measured 413.6us R8 kernel.
//   partial[nb][b,s] = sum_{u in 128-slice nb} Vw[u]*tanh(enc@Wh + sh2 + cov*Wc)
// Block 128(s) x 128(u), 8 warps (2m x 4n), warp tile 64x32 (4mt x 4nt).
// K-chunks of 32: A = LDG fp32 -> cvt -> STS fp16 (single buffer, reg
// prefetch); B = cp.async fp16 from g_WhTh, double-buffered. 2 CTAs/SM.
// blockIdx.x = mb*4 + nb (nb fastest -> enc tile shared via L2).
// ============================================================================
__global__ __launch_bounds__(256) void k_score_f16(
    const float* __restrict__ enc, const float* __restrict__ cov,
    const float* __restrict__ Wc, const float* __restrict__ Vw)
{
    __shared__ __half Ash[128 * ASTR];       // 10.0 KB
    __shared__ __half Bsh[2][128 * BSTR];    // 2 x 10.0 KB
    __shared__ float covs[128];
    __shared__ float sh2s[128], Wcs[128], Vws[128];
    __shared__ float red[128][4];

    const int tid  = threadIdx.x;
    const int lane = tid & 31;
    const int warp = tid >> 5;
    const int wm   = warp >> 2;          // 0..1 -> 64-row slice
    const int wn   = warp & 3;           // 0..3 -> 32-col slice

    const int gb = blockIdx.x;
    const int nb = gb & 3;               // u-slice (128 wide)
    const int mb = gb >> 2;
    const int b  = mb >> 4;              // 16 m-blocks per batch
    const int s0 = (mb & 15) * 128;
    const int u0 = nb * 128;

    const float*  X  = enc + ((size_t)b * S_ + s0) * D_;
    const __half* Bg = g_WhTh + (size_t)u0 * D_;

    if (tid < 128) covs[tid] = cov[(size_t)b * S_ + s0 + tid];
    else {
        int u = tid - 128;
        sh2s[u] = g_sh2[b * U_ + u0 + u];
        Wcs[u]  = Wc[u0 + u];
        Vws[u]  = Vw[u0 + u];
    }

    float acc[4][4][4];
    #pragma unroll
    for (int mt = 0; mt < 4; ++mt)
        #pragma unroll
        for (int nt = 0; nt < 4; ++nt)
            #pragma unroll
            for (int i = 0; i < 4; ++i) acc[mt][nt][i] = 0.f;

    // A prefetch registers: 4 float4 per thread (128 rows x 8 quads)
    float4 av[4];
    #pragma unroll
    for (int l = 0; l < 4; ++l) {
        int slot = tid + l * 256;
        int row = slot >> 3, q = slot & 7;
        av[l] = *(const float4*)(X + (size_t)row * D_ + q * 4);
    }
    // B chunk 0 via cp.async
    #pragma unroll
    for (int l = 0; l < 2; ++l) {
        int slot = tid + l * 256;
        int row = slot >> 2, seg = slot & 3;
        cp_async16(&Bsh[0][row * BSTR + seg * 8], Bg + (size_t)row * D_ + seg * 8);
    }
    CP_COMMIT();

    for (int kt = 0; kt < NKT; ++kt) {
        const int cur = kt & 1;
        __syncthreads();   // all warps done reading Ash (iter kt-1)
        // store A(kt) fp16 into Ash
        #pragma unroll
        for (int l = 0; l < 4; ++l) {
            int slot = tid + l * 256;
            int row = slot >> 3, q = slot & 7;
            __half2 h0 = __floats2half2_rn(av[l].x, av[l].y);
            __half2 h1 = __floats2half2_rn(av[l].z, av[l].w);
            *(__half2*)&Ash[row * ASTR + q * 4]     = h0;
            *(__half2*)&Ash[row * ASTR + q * 4 + 2] = h1;
        }
        if (kt + 1 < NKT) {
            // prefetch A(kt+1) into regs
            #pragma unroll
            for (int l = 0; l < 4; ++l) {
                int slot = tid + l * 256;
                int row = slot >> 3, q = slot & 7;
                av[l] = *(const float4*)(X + (size_t)row * D_ + (kt + 1) * KT + q * 4);
            }
            // B(kt+1) cp.async into other buffer
            #pragma unroll
            for (int l = 0; l < 2; ++l) {
                int slot = tid + l * 256;
                int row = slot >> 2, seg = slot & 3;
                cp_async16(&Bsh[cur ^ 1][row * BSTR + seg * 8],
                           Bg + (size_t)row * D_ + (kt + 1) * KT + seg * 8);
            }
            CP_COMMIT();
            CP_WAIT(1);    // B(kt) arrived
        } else {
            CP_WAIT(0);
        }
        __syncthreads();

        const __half* Bc = Bsh[cur];
        #pragma unroll
        for (int kk = 0; kk < 2; ++kk) {        // two k16 steps per chunk
            uint32_t a[4][4];
            #pragma unroll
            for (int mt = 0; mt < 4; ++mt) {
                int r = wm * 64 + mt * 16 + (lane >> 2);
                int c = kk * 16 + 2 * (lane & 3);
                a[mt][0] = *(const uint32_t*)&Ash[r * ASTR + c];
                a[mt][1] = *(const uint32_t*)&Ash[(r + 8) * ASTR + c];
                a[mt][2] = *(const uint32_t*)&Ash[r * ASTR + c + 8];
                a[mt][3] = *(const uint32_t*)&Ash[(r + 8) * ASTR + c + 8];
            }
            uint32_t bf[4][2];
            #pragma unroll
            for (int nt = 0; nt < 4; ++nt) {
                int n = wn * 32 + nt * 8 + (lane >> 2);
                int c = kk * 16 + 2 * (lane & 3);
                bf[nt][0] = *(const uint32_t*)&Bc[n * BSTR + c];
                bf[nt][1] = *(const uint32_t*)&Bc[n * BSTR + c + 8];
            }
            #pragma unroll
            for (int mt = 0; mt < 4; ++mt)
                #pragma unroll
                for (int nt = 0; nt < 4; ++nt)
                    mma_f16(acc[mt][nt][0], acc[mt][nt][1],
                            acc[mt][nt][2], acc[mt][nt][3],
                            a[mt][0], a[mt][1], a[mt][2], a[mt][3],
                            bf[nt][0], bf[nt][1]);
        }
    }

    // --- epilogue: e -> tanh -> *Vw -> per-row partial sums ---
    float psum[8];
    #pragma unroll
    for (int i = 0; i < 8; ++i) psum[i] = 0.f;
    #pragma unroll
    for (int mt = 0; mt < 4; ++mt) {
        int r_lo = wm * 64 + mt * 16 + (lane >> 2);
        float cv_lo = covs[r_lo];
        float cv_hi = covs[r_lo + 8];
        #pragma unroll
        for (int nt = 0; nt < 4; ++nt) {
            int uc = wn * 32 + nt * 8 + 2 * (lane & 3);
            #pragma unroll
            for (int j = 0; j < 2; ++j) {
                float s2 = sh2s[uc + j], wc = Wcs[uc + j], vw = Vws[uc + j];
                float e0 = acc[mt][nt][j]     + s2 + cv_lo * wc;
                float e1 = acc[mt][nt][2 + j] + s2 + cv_hi * wc;
                psum[2 * mt]     = fmaf(vw, tanh_fast(e0), psum[2 * mt]);
                psum[2 * mt + 1] = fmaf(vw, tanh_fast(e1), psum[2 * mt + 1]);
            }
        }
    }
    #pragma unroll
    for (int i = 0; i < 8; ++i) {
        psum[i] += __shfl_xor_sync(0xffffffff, psum[i], 1);
        psum[i] += __shfl_xor_sync(0xffffffff, psum[i], 2);
    }
    __syncthreads();
    if ((lane & 3) == 0) {
        #pragma unroll
        for (int mt = 0; mt < 4; ++mt) {
            int r = wm * 64 + mt * 16 + (lane >> 2);
            red[r][wn]     = psum[2 * mt];
            red[r + 8][wn] = psum[2 * mt + 1];
        }
    }
    __syncthreads();
    if (tid < 128) {
        g_scorep[(size_t)nb * BS_ + (size_t)b * S_ + s0 + tid] =
            red[tid][0] + red[tid][1] + red[tid][2] + red[tid][3];
    }
}

// ============================================================================
// Kernel 3: fold 4 score partials; masked renormalized softmax + coverage.
// 1024 threads (measured 17.2 -> 8.4 us vs 256 threads).
// ============================================================================
__global__ __launch_bounds__(1024) void k_softmax(
    const float* __restrict__ mask, const float* __restrict__ cov,
    float* __restrict__ attn_out, float* __restrict__ cov_out)
{
    __shared__ float sred[1024];
    __shared__ float ps[S_];
    int b = blockIdx.x;
    int tid = threadIdx.x;

    float m = -1e30f;
    for (int s = tid; s < S_; s += 1024) {
        float sc = 0.f;
        #pragma unroll
        for (int n = 0; n < 4; ++n)
            sc += g_scorep[(size_t)n * BS_ + (size_t)b * S_ + s];
        ps[s] = sc;
        m = fmaxf(m, sc);
    }
    sred[tid] = m; __syncthreads();
    for (int off = 512; off; off >>= 1) {
        if (tid < off) sred[tid] = fmaxf(sred[tid], sred[tid + off]);
        __syncthreads();
    }
    m = sred[0]; __syncthreads();

    float sum = 0.f;
    for (int s = tid; s < S_; s += 1024) {
        float p = expf(ps[s] - m) * mask[(size_t)b * S_ + s];
        ps[s] = p;
        sum += p;
    }
    sred[tid] = sum; __syncthreads();
    for (int off = 512; off; off >>= 1) {
        if (tid < off) sred[tid] += sred[tid + off];
        __syncthreads();
    }
    float inv = 1.f / sred[0];

    for (int s = tid; s < S_; s += 1024) {
        float a = ps[s] * inv;
        attn_out[(size_t)b * S_ + s] = a;
        cov_out[(size_t)b * S_ + s]  = a + cov[(size_t)b * S_ + s];
    }
}

// ============================================================================
// Kernel 4: partial context over 32 s-chunks of 64.
// ============================================================================
__global__ __launch_bounds__(128) void k_ctx(
    const float* __restrict__ enc, const float* __restrict__ attn)
{
    __shared__ float as[64];
    int b = blockIdx.x;
    int ch = blockIdx.y;
    int tid = threadIdx.x;
    int s0 = ch * 64;
    if (tid < 64) as[tid] = attn[(size_t)b * S_ + s0 + tid];
    __syncthreads();

    const float4* ep = (const float4*)(enc + ((size_t)b * S_ + s0) * D_) + tid;
    float4 acc = make_float4(0.f, 0.f, 0.f, 0.f);
    #pragma unroll 8
    for (int s = 0; s < 64; ++s) {
        float a = as[s];
        float4 v = ep[(size_t)s * (D_ / 4)];
        acc.x = fmaf(a, v.x, acc.x);
        acc.y = fmaf(a, v.y, acc.y);
        acc.z = fmaf(a, v.z, acc.z);
        acc.w = fmaf(a, v.w, acc.w);
    }
    *(float4*)&g_ctxp[((size_t)ch * B_ + b) * D_ + tid * 4] = acc;
}

__global__ __launch_bounds__(256) void k_ctx_red(float* __restrict__ ctx_out)
{
    int i = blockIdx.x * 256 + threadIdx.x;
    if (i < B_ * D_) {
        float s = 0.f;
        #pragma unroll
        for (int c = 0; c < 32; ++c) s += g_ctxp[c * B_ * D_ + i];
        ctx_out[i] = s;
    }
}

// ============================================================================
// launch
// ============================================================================
extern "C" void kernel_launch(void* const* d_in, const int* in_sizes, int n_in,
                              void* d_out, int out_size)
{
    const float* dec  = (const float*)d_in[0];   // (B,D)
    const float* enc  = (const float*)d_in[1];   // (B,S,D)
    const float* mask = (const float*)d_in[2];   // (B,S)
    const float* cov  = (const float*)d_in[3];   // (B,S,1)
    const float* Wh   = (const float*)d_in[4];   // (D,U)
    const float* bh   = (const float*)d_in[5];   // (U)
    const float* Ws   = (const float*)d_in[6];   // (D,U)
    const float* bs   = (const float*)d_in[7];   // (U)
    const float* Wc   = (const float*)d_in[8];   // (1,U)
    const float* bc   = (const float*)d_in[9];   // (U)
    const float* Vw   = (const float*)d_in[10];  // (U,1)
    // d_in[11] = bv: constant shift, cancels under renormalized softmax.

    float* out_ctx  = (float*)d_out;                     // (B,D)
    float* out_attn = (float*)d_out + B_ * D_;           // (B,S)
    float* out_cov  = (float*)d_out + B_ * D_ + B_ * S_; // (B,S,1)

    k_prepWh<<<dim3(16, 16), 256>>>(Wh);
    k_sh2<<<dim3(B_, 4), 128>>>(dec, Ws, bs, bh, bc);
    k_score_f16<<<(BS_ / 128) * 4, 256>>>(enc, cov, Wc, Vw);
    k_softmax<<<B_, 1024>>>(mask, cov, out_attn, out_cov);
    k_ctx<<<dim3(B_, 32), 128>>>(enc, out_attn);
    k_ctx_red<<<(B_ * D_ + 255) / 256, 256>>>(out_ctx);
}